// round 2
// baseline (speedup 1.0000x reference)
#include <cuda_runtime.h>

#define Dh 128
#define NHEAD 16
#define NB 2
#define SEQ 2048
#define NHD (NHEAD*Dh)     // 2048
#define MROWS (NB*SEQ)     // 4096

// Scratch (no allocations allowed): Q,K,V and ctx in (B,H,S,D) layout.
__device__ float g_QKV[3][(size_t)NB*NHEAD*SEQ*Dh];
__device__ float g_CTX[(size_t)NB*NHEAD*SEQ*Dh];

// ---------------------------------------------------------------------------
// QKV projection: Y[b,h,s,d] = sum_k X[b,s,k] * W[h*Dh+d, k] + bias[h*Dh+d]
// X: (B*S, 128) row-major; W: (2048, 128) row-major (torch Linear weight).
// 64x64 output tile per block, full K=128 in smem, 256 threads, 4x4 per thread.
// ---------------------------------------------------------------------------
__global__ __launch_bounds__(256) void qkv_gemm_kernel(
    const float* __restrict__ X, const float* __restrict__ W,
    const float* __restrict__ bias, int which)
{
    extern __shared__ float sm[];
    float* Xs = sm;             // 64 x 129
    float* Ws = sm + 64*129;    // 64 x 129

    const int m0 = blockIdx.y * 64;
    const int n0 = blockIdx.x * 64;
    const int tid = threadIdx.x;

    for (int i = tid; i < 64*32; i += 256) {
        int r = i >> 5, c = (i & 31) << 2;
        float4 v = *(const float4*)(X + (size_t)(m0 + r)*Dh + c);
        Xs[r*129 + c]   = v.x; Xs[r*129 + c+1] = v.y;
        Xs[r*129 + c+2] = v.z; Xs[r*129 + c+3] = v.w;
        float4 w = *(const float4*)(W + (size_t)(n0 + r)*Dh + c);
        Ws[r*129 + c]   = w.x; Ws[r*129 + c+1] = w.y;
        Ws[r*129 + c+2] = w.z; Ws[r*129 + c+3] = w.w;
    }
    __syncthreads();

    const int tx = tid & 15, ty = tid >> 4;
    float acc[4][4] = {};
    #pragma unroll 4
    for (int k = 0; k < Dh; ++k) {
        float a[4];
        #pragma unroll
        for (int i = 0; i < 4; ++i) a[i] = Xs[(ty*4 + i)*129 + k];
        #pragma unroll
        for (int j = 0; j < 4; ++j) {
            float bv = Ws[(tx + 16*j)*129 + k];
            #pragma unroll
            for (int i = 0; i < 4; ++i) acc[i][j] += a[i] * bv;
        }
    }

    float* Y = g_QKV[which];
    #pragma unroll
    for (int i = 0; i < 4; ++i) {
        int m = m0 + ty*4 + i;
        int b = m >> 11, s = m & 2047;
        #pragma unroll
        for (int j = 0; j < 4; ++j) {
            int n = n0 + tx + 16*j;
            int h = n >> 7, d = n & 127;
            Y[(((size_t)(b*NHEAD + h))*SEQ + s)*Dh + d] = acc[i][j] + bias[n];
        }
    }
}

// ---------------------------------------------------------------------------
// Fused attention per (b, h, 64 q-rows):
//  phase 1: scores = QK^T*scale + mask*(-1e9); write raw scores into the
//           weights output region; track per-row online (max, sumexp).
//  reduce:  combine partial (m,l) across the 16 tx lanes per row.
//  phase 2: re-read raw scores (L2-resident), w = exp(s-m)/l, write final
//           weights back, accumulate ctx += w @ V.
// ---------------------------------------------------------------------------
__global__ __launch_bounds__(256) void attn_kernel(
    const int* __restrict__ mask, float* __restrict__ weights)
{
    extern __shared__ float sm[];
    float* Qs   = sm;                  // 64*129  (Q tile, K-major stride 129)
    float* Ts   = Qs + 64*129;         // 64*132  (K tile: stride 129 / V tile: stride 132)
    float* wS   = Ts + 64*132;         // 64*65   (softmax weights tile)
    float* redm = wS + 64*65;          // 64*17
    float* redl = redm + 64*17;        // 64*17
    float* mrow = redl + 64*17;        // 64
    float* linv = mrow + 64;           // 64

    const int s0 = blockIdx.x * 64;
    const int h  = blockIdx.y;
    const int b  = blockIdx.z;
    const int tid = threadIdx.x;
    const int tx = tid & 15, ty = tid >> 4;

    const size_t bh = (size_t)(b*NHEAD + h);
    const float* Qg = g_QKV[0] + bh*SEQ*Dh;
    const float* Kg = g_QKV[1] + bh*SEQ*Dh;
    const float* Vg = g_QKV[2] + bh*SEQ*Dh;
    const int*   mb = mask + (size_t)b*SEQ*SEQ;
    float*       wb = weights + bh*SEQ*SEQ;

    // Load Q tile (64 x 128)
    for (int i = tid; i < 64*32; i += 256) {
        int r = i >> 5, c = (i & 31) << 2;
        float4 v = *(const float4*)(Qg + (size_t)(s0 + r)*Dh + c);
        Qs[r*129 + c]   = v.x; Qs[r*129 + c+1] = v.y;
        Qs[r*129 + c+2] = v.z; Qs[r*129 + c+3] = v.w;
    }

    float mloc[4], lloc[4];
    #pragma unroll
    for (int i = 0; i < 4; ++i) { mloc[i] = -1e30f; lloc[i] = 0.f; }
    const float scale = 0.08838834764831845f;   // 1/sqrt(128)

    // ---------------- phase 1 ----------------
    for (int t0 = 0; t0 < SEQ; t0 += 64) {
        __syncthreads();
        for (int i = tid; i < 64*32; i += 256) {
            int r = i >> 5, c = (i & 31) << 2;
            float4 v = *(const float4*)(Kg + (size_t)(t0 + r)*Dh + c);
            Ts[r*129 + c]   = v.x; Ts[r*129 + c+1] = v.y;
            Ts[r*129 + c+2] = v.z; Ts[r*129 + c+3] = v.w;
        }
        __syncthreads();

        float acc[4][4] = {};
        #pragma unroll 4
        for (int k = 0; k < Dh; ++k) {
            float a[4];
            #pragma unroll
            for (int i = 0; i < 4; ++i) a[i] = Qs[(ty*4 + i)*129 + k];
            #pragma unroll
            for (int j = 0; j < 4; ++j) {
                float bv = Ts[(tx + 16*j)*129 + k];
                #pragma unroll
                for (int i = 0; i < 4; ++i) acc[i][j] += a[i] * bv;
            }
        }

        #pragma unroll
        for (int i = 0; i < 4; ++i) {
            int rg = s0 + ty*4 + i;
            float nm = mloc[i];
            #pragma unroll
            for (int j = 0; j < 4; ++j) {
                int t = t0 + tx + 16*j;
                float sc = acc[i][j]*scale + (float)mb[(size_t)rg*SEQ + t] * (-1e9f);
                acc[i][j] = sc;
                wb[(size_t)rg*SEQ + t] = sc;       // raw score (rescaled in phase 2)
                nm = fmaxf(nm, sc);
            }
            if (nm > mloc[i]) { lloc[i] *= __expf(mloc[i] - nm); mloc[i] = nm; }
            #pragma unroll
            for (int j = 0; j < 4; ++j) lloc[i] += __expf(acc[i][j] - nm);
        }
    }

    // ---------------- reduce (m,l) across tx ----------------
    #pragma unroll
    for (int i = 0; i < 4; ++i) {
        redm[(ty*4 + i)*17 + tx] = mloc[i];
        redl[(ty*4 + i)*17 + tx] = lloc[i];
    }
    __syncthreads();
    if (tid < 64) {
        float m = -1e30f;
        for (int x = 0; x < 16; ++x) m = fmaxf(m, redm[tid*17 + x]);
        float l = 0.f;
        for (int x = 0; x < 16; ++x) l += redl[tid*17 + x] * __expf(redm[tid*17 + x] - m);
        mrow[tid] = m;
        linv[tid] = 1.0f / l;
    }
    __syncthreads();

    // ---------------- phase 2 ----------------
    float ctx[4][8] = {};
    const int cx = tx * 8;
    for (int t0 = 0; t0 < SEQ; t0 += 64) {
        __syncthreads();
        // V tile (stride 132 -> aligned float4)
        for (int i = tid; i < 64*32; i += 256) {
            int r = i >> 5, c = (i & 31) << 2;
            float4 v = *(const float4*)(Vg + (size_t)(t0 + r)*Dh + c);
            *(float4*)&Ts[r*132 + c] = v;
        }
        // finalize softmax weights for this tile
        #pragma unroll
        for (int i = 0; i < 4; ++i) {
            int r = ty*4 + i;
            int rg = s0 + r;
            float m = mrow[r], li = linv[r];
            #pragma unroll
            for (int j = 0; j < 4; ++j) {
                int t = t0 + tx + 16*j;
                float sc = wb[(size_t)rg*SEQ + t];
                float w = __expf(sc - m) * li;
                wb[(size_t)rg*SEQ + t] = w;
                wS[r*65 + tx + 16*j] = w;
            }
        }
        __syncthreads();
        // ctx += w @ V
        #pragma unroll 2
        for (int tt = 0; tt < 64; ++tt) {
            float4 v0 = *(const float4*)&Ts[tt*132 + cx];
            float4 v1 = *(const float4*)&Ts[tt*132 + cx + 4];
            #pragma unroll
            for (int i = 0; i < 4; ++i) {
                float w = wS[(ty*4 + i)*65 + tt];
                ctx[i][0] += w*v0.x; ctx[i][1] += w*v0.y;
                ctx[i][2] += w*v0.z; ctx[i][3] += w*v0.w;
                ctx[i][4] += w*v1.x; ctx[i][5] += w*v1.y;
                ctx[i][6] += w*v1.z; ctx[i][7] += w*v1.w;
            }
        }
    }

    float* Cb = g_CTX + bh*SEQ*Dh;
    #pragma unroll
    for (int i = 0; i < 4; ++i) {
        #pragma unroll
        for (int j = 0; j < 8; j += 4) {
            float4 v = make_float4(ctx[i][j], ctx[i][j+1], ctx[i][j+2], ctx[i][j+3]);
            *(float4*)(Cb + (size_t)(s0 + ty*4 + i)*Dh + cx + j) = v;
        }
    }
}

// ---------------------------------------------------------------------------
// Output projection: out[b,s,n] = sum_{h,d} ctx[b,h,s,d] * Wd[n, h*Dh+d] + bd[n]
// ---------------------------------------------------------------------------
__global__ __launch_bounds__(256) void out_gemm_kernel(
    const float* __restrict__ Wd, const float* __restrict__ bd,
    float* __restrict__ out)
{
    extern __shared__ float sm[];
    float* Xs = sm;             // 64 x 129
    float* Ws = sm + 64*129;    // 64 x 129

    const int m0 = blockIdx.y * 64;
    const int n0 = blockIdx.x * 64;     // 0 or 64
    const int tid = threadIdx.x;
    const int tx = tid & 15, ty = tid >> 4;
    const int b = m0 >> 11;
    const int sbase = m0 & 2047;

    float acc[4][4] = {};
    for (int kt = 0; kt < NHEAD; ++kt) {
        __syncthreads();
        for (int i = tid; i < 64*32; i += 256) {
            int r = i >> 5, c = (i & 31) << 2;
            float4 v = *(const float4*)(g_CTX +
                (((size_t)(b*NHEAD + kt))*SEQ + sbase + r)*Dh + c);
            Xs[r*129 + c]   = v.x; Xs[r*129 + c+1] = v.y;
            Xs[r*129 + c+2] = v.z; Xs[r*129 + c+3] = v.w;
            float4 w = *(const float4*)(Wd + (size_t)(n0 + r)*NHD + kt*Dh + c);
            Ws[r*129 + c]   = w.x; Ws[r*129 + c+1] = w.y;
            Ws[r*129 + c+2] = w.z; Ws[r*129 + c+3] = w.w;
        }
        __syncthreads();
        #pragma unroll 4
        for (int k = 0; k < Dh; ++k) {
            float a[4];
            #pragma unroll
            for (int i = 0; i < 4; ++i) a[i] = Xs[(ty*4 + i)*129 + k];
            #pragma unroll
            for (int j = 0; j < 4; ++j) {
                float bv = Ws[(tx + 16*j)*129 + k];
                #pragma unroll
                for (int i = 0; i < 4; ++i) acc[i][j] += a[i] * bv;
            }
        }
    }

    #pragma unroll
    for (int i = 0; i < 4; ++i) {
        int m = m0 + ty*4 + i;
        #pragma unroll
        for (int j = 0; j < 4; ++j) {
            int n = n0 + tx + 16*j;
            out[(size_t)m*Dh + n] = acc[i][j] + bd[n];
        }
    }
}

// ---------------------------------------------------------------------------
extern "C" void kernel_launch(void* const* d_in, const int* in_sizes, int n_in,
                              void* d_out, int out_size)
{
    (void)in_sizes; (void)n_in; (void)out_size;
    const float* x    = (const float*)d_in[0];
    const int*   mask = (const int*)  d_in[1];
    const float* Wq   = (const float*)d_in[2];
    const float* bq   = (const float*)d_in[3];
    const float* Wk   = (const float*)d_in[4];
    const float* bk   = (const float*)d_in[5];
    const float* Wv   = (const float*)d_in[6];
    const float* bv   = (const float*)d_in[7];
    const float* Wd   = (const float*)d_in[8];
    const float* bd   = (const float*)d_in[9];

    float* out     = (float*)d_out;                         // (B,S,D)
    float* weights = out + (size_t)NB*SEQ*Dh;               // (B,H,S,S)

    const size_t smem_gemm = (size_t)2*64*129*sizeof(float);     // 66048 B
    const size_t smem_attn = (size_t)(64*129 + 64*132 + 64*65 +
                                      64*17*2 + 128) * sizeof(float);  // 92672 B

    cudaFuncSetAttribute(qkv_gemm_kernel,
        cudaFuncAttributeMaxDynamicSharedMemorySize, (int)smem_gemm);
    cudaFuncSetAttribute(attn_kernel,
        cudaFuncAttributeMaxDynamicSharedMemorySize, (int)smem_attn);
    cudaFuncSetAttribute(out_gemm_kernel,
        cudaFuncAttributeMaxDynamicSharedMemorySize, (int)smem_gemm);

    dim3 blk(256);
    dim3 g1(NHD/64, MROWS/64);          // (32, 64)
    qkv_gemm_kernel<<<g1, blk, smem_gemm>>>(x, Wq, bq, 0);
    qkv_gemm_kernel<<<g1, blk, smem_gemm>>>(x, Wk, bk, 1);
    qkv_gemm_kernel<<<g1, blk, smem_gemm>>>(x, Wv, bv, 2);

    dim3 g2(SEQ/64, NHEAD, NB);         // (32, 16, 2)
    attn_kernel<<<g2, blk, smem_attn>>>(mask, weights);

    dim3 g3(Dh/64, MROWS/64);           // (2, 64)
    out_gemm_kernel<<<g3, blk, smem_gemm>>>(Wd, bd, out);
}

// round 4
// speedup vs baseline: 2.2682x; 2.2682x over previous
#include <cuda_runtime.h>

#define Dh 128
#define NHEAD 16
#define NB 2
#define SEQ 2048
#define NHD (NHEAD*Dh)
#define MROWS (NB*SEQ)

__device__ float g_QKV[3][(size_t)NB*NHEAD*SEQ*Dh];
__device__ float g_CTX[(size_t)NB*NHEAD*SEQ*Dh];

#define LDA 132
#define LDV 136

__device__ __forceinline__ unsigned f2tf32(float f){
    unsigned r; asm("cvt.rna.tf32.f32 %0, %1;" : "=r"(r) : "f"(f)); return r;
}
__device__ __forceinline__ void mma8(float* d, const unsigned* a, unsigned b0, unsigned b1){
    asm volatile("mma.sync.aligned.m16n8k8.row.col.f32.tf32.tf32.f32 "
        "{%0,%1,%2,%3},{%4,%5,%6,%7},{%8,%9},{%0,%1,%2,%3};"
        : "+f"(d[0]), "+f"(d[1]), "+f"(d[2]), "+f"(d[3])
        : "r"(a[0]), "r"(a[1]), "r"(a[2]), "r"(a[3]), "r"(b0), "r"(b1));
}

// 128x128 f32 tile -> smem tf32 (row-major, ld=LDA), optional scale
__device__ __forceinline__ void load_tile(unsigned* dst, const float* src, int srcStride,
                                          float scale, int tid){
    #pragma unroll
    for (int it = 0; it < 16; ++it){
        int idx = tid + it*256;
        int r = idx >> 5, c = (idx & 31) << 2;
        float4 v = *(const float4*)(src + (size_t)r*srcStride + c);
        uint4 u = make_uint4(f2tf32(v.x*scale), f2tf32(v.y*scale),
                             f2tf32(v.z*scale), f2tf32(v.w*scale));
        *(uint4*)(dst + r*LDA + c) = u;
    }
}
// same but ld=LDV (for V)
__device__ __forceinline__ void load_tile_v(unsigned* dst, const float* src, int srcStride, int tid){
    #pragma unroll
    for (int it = 0; it < 16; ++it){
        int idx = tid + it*256;
        int r = idx >> 5, c = (idx & 31) << 2;
        float4 v = *(const float4*)(src + (size_t)r*srcStride + c);
        uint4 u = make_uint4(f2tf32(v.x), f2tf32(v.y), f2tf32(v.z), f2tf32(v.w));
        *(uint4*)(dst + r*LDV + c) = u;
    }
}

// warp GEMM over one 128x128x128 tile: acc[2][8][4] += A(32x128) * B^T (B stored [n][k])
__device__ __forceinline__ void wgemm(float acc[2][8][4], const unsigned* As, const unsigned* Bs,
                                      int m0w, int n0w, int g, int t4){
    #pragma unroll 4
    for (int kk = 0; kk < 16; ++kk){
        unsigned a[2][4];
        #pragma unroll
        for (int mi = 0; mi < 2; ++mi){
            const unsigned* p = As + (m0w + mi*16 + g)*LDA + kk*8 + t4;
            a[mi][0] = p[0];       a[mi][2] = p[4];
            a[mi][1] = p[8*LDA];   a[mi][3] = p[8*LDA + 4];
        }
        #pragma unroll
        for (int j = 0; j < 8; ++j){
            const unsigned* p = Bs + (n0w + j*8 + g)*LDA + kk*8 + t4;
            unsigned b0 = p[0], b1 = p[4];
            mma8(acc[0][j], a[0], b0, b1);
            mma8(acc[1][j], a[1], b0, b1);
        }
    }
}
// PV variant: B = V stored [t][d] (k-major rows), ld=LDV
__device__ __forceinline__ void wgemm_v(float acc[2][8][4], const unsigned* As, const unsigned* Vs,
                                        int m0w, int n0w, int g, int t4){
    #pragma unroll 4
    for (int kk = 0; kk < 16; ++kk){
        unsigned a[2][4];
        #pragma unroll
        for (int mi = 0; mi < 2; ++mi){
            const unsigned* p = As + (m0w + mi*16 + g)*LDA + kk*8 + t4;
            a[mi][0] = p[0];       a[mi][2] = p[4];
            a[mi][1] = p[8*LDA];   a[mi][3] = p[8*LDA + 4];
        }
        #pragma unroll
        for (int j = 0; j < 8; ++j){
            const unsigned* p = Vs + (kk*8 + t4)*LDV + n0w + j*8 + g;
            unsigned b0 = p[0], b1 = p[4*LDV];
            mma8(acc[0][j], a[0], b0, b1);
            mma8(acc[1][j], a[1], b0, b1);
        }
    }
}

// ---------------- QKV projection (tf32 mma), Y in (B,H,S,D) ----------------
__global__ __launch_bounds__(256) void proj_tc(const float* __restrict__ X,
                                               const float* __restrict__ W,
                                               const float* __restrict__ bias, int which)
{
    extern __shared__ unsigned sm[];
    unsigned* As = sm;
    unsigned* Bs = sm + 128*LDA;
    const int tid = threadIdx.x, lane = tid & 31, g = lane >> 2, t4 = lane & 3, w = tid >> 5;
    const int m0w = (w & 3) * 32, n0w = (w >> 2) * 64;
    const int m0 = blockIdx.y * 128, n0 = blockIdx.x * 128;

    load_tile(As, X + (size_t)m0*Dh, Dh, 1.f, tid);
    load_tile(Bs, W + (size_t)n0*Dh, Dh, 1.f, tid);
    __syncthreads();

    float acc[2][8][4] = {};
    wgemm(acc, As, Bs, m0w, n0w, g, t4);

    const int b = m0 >> 11, sbase = m0 & 2047, h = n0 >> 7;
    float* Yb = g_QKV[which] + ((size_t)(b*NHEAD + h)*SEQ)*Dh;
    #pragma unroll
    for (int mi = 0; mi < 2; ++mi)
        #pragma unroll
        for (int half = 0; half < 2; ++half){
            int rl = m0w + mi*16 + half*8 + g;
            float* Yr = Yb + (size_t)(sbase + rl)*Dh;
            #pragma unroll
            for (int j = 0; j < 8; ++j){
                int d = n0w + j*8 + 2*t4;
                float2 v = make_float2(acc[mi][j][half*2]   + bias[n0 + d],
                                       acc[mi][j][half*2+1] + bias[n0 + d + 1]);
                *(float2*)(Yr + d) = v;
            }
        }
}

// ---------------- fused mma attention ----------------
__global__ __launch_bounds__(256, 1) void attn_mma(const int* __restrict__ mask,
                                                   float* __restrict__ weights)
{
    extern __shared__ unsigned sm[];
    unsigned* Qs = sm;                  // 128 x LDA (persistent, pre-scaled)
    unsigned* Ks = sm + 128*LDA;        // K tile; reused as w tile in phase 2
    unsigned* Vs = sm + 2*128*LDA;      // 128 x LDV
    __shared__ float lpart[128][2];
    __shared__ float linvs[128];

    const int tid = threadIdx.x, lane = tid & 31, g = lane >> 2, t4 = lane & 3, w = tid >> 5;
    const int m0w = (w & 3) * 32, n0w = (w >> 2) * 64;
    const int h = blockIdx.x, q0 = blockIdx.y * 128, b = blockIdx.z;
    const size_t bh = (size_t)(b*NHEAD + h);
    const float* Qg = g_QKV[0] + bh*SEQ*Dh + (size_t)q0*Dh;
    const float* Kg = g_QKV[1] + bh*SEQ*Dh;
    const float* Vg = g_QKV[2] + bh*SEQ*Dh;
    const int*   mb = mask + (size_t)b*SEQ*SEQ;
    float*       wb = weights + bh*(size_t)SEQ*SEQ;

    load_tile(Qs, Qg, Dh, 0.08838834764831845f, tid);   // Q / sqrt(D)

    float lsum[2][2] = {{0.f,0.f},{0.f,0.f}};

    // ---- phase 1: row sums of exp ----
    for (int t0 = 0; t0 < SEQ; t0 += 128){
        __syncthreads();
        load_tile(Ks, Kg + (size_t)t0*Dh, Dh, 1.f, tid);
        __syncthreads();
        float acc[2][8][4] = {};
        wgemm(acc, Qs, Ks, m0w, n0w, g, t4);
        #pragma unroll
        for (int mi = 0; mi < 2; ++mi){
            int r0 = q0 + m0w + mi*16 + g;
            const int* mr0 = mb + (size_t)r0*SEQ + t0;
            const int* mr1 = mr0 + 8*SEQ;
            #pragma unroll
            for (int j = 0; j < 8; ++j){
                int cc = n0w + j*8 + 2*t4;
                int2 mA = *(const int2*)(mr0 + cc);
                int2 mB = *(const int2*)(mr1 + cc);
                lsum[mi][0] += __expf(fmaf((float)mA.x, -1e9f, acc[mi][j][0]))
                             + __expf(fmaf((float)mA.y, -1e9f, acc[mi][j][1]));
                lsum[mi][1] += __expf(fmaf((float)mB.x, -1e9f, acc[mi][j][2]))
                             + __expf(fmaf((float)mB.y, -1e9f, acc[mi][j][3]));
            }
        }
    }

    // reduce l across the 4 lanes of each group, then across the 2 n-warps
    #pragma unroll
    for (int mi = 0; mi < 2; ++mi)
        #pragma unroll
        for (int half = 0; half < 2; ++half){
            float v = lsum[mi][half];
            v += __shfl_xor_sync(0xffffffffu, v, 1);
            v += __shfl_xor_sync(0xffffffffu, v, 2);
            if (t4 == 0) lpart[m0w + mi*16 + half*8 + g][w >> 2] = v;
        }
    __syncthreads();
    if (tid < 128) linvs[tid] = 1.0f / (lpart[tid][0] + lpart[tid][1]);
    __syncthreads();

    // ---- phase 2: recompute scores, write weights, PV ----
    float ctx[2][8][4] = {};
    for (int t0 = 0; t0 < SEQ; t0 += 128){
        __syncthreads();
        load_tile(Ks, Kg + (size_t)t0*Dh, Dh, 1.f, tid);
        load_tile_v(Vs, Vg + (size_t)t0*Dh, Dh, tid);
        __syncthreads();
        float acc[2][8][4] = {};
        wgemm(acc, Qs, Ks, m0w, n0w, g, t4);
        __syncthreads();                 // all QK reads done -> Ks reusable as w tile
        #pragma unroll
        for (int mi = 0; mi < 2; ++mi){
            int rl0 = m0w + mi*16 + g;
            int r0 = q0 + rl0;
            float li0 = linvs[rl0], li1 = linvs[rl0 + 8];
            const int* mr0 = mb + (size_t)r0*SEQ + t0;
            const int* mr1 = mr0 + 8*SEQ;
            float* wr0 = wb + (size_t)r0*SEQ + t0;
            float* wr1 = wr0 + 8*SEQ;
            #pragma unroll
            for (int j = 0; j < 8; ++j){
                int cc = n0w + j*8 + 2*t4;
                int2 mA = *(const int2*)(mr0 + cc);
                int2 mB = *(const int2*)(mr1 + cc);
                float w00 = __expf(fmaf((float)mA.x, -1e9f, acc[mi][j][0])) * li0;
                float w01 = __expf(fmaf((float)mA.y, -1e9f, acc[mi][j][1])) * li0;
                float w10 = __expf(fmaf((float)mB.x, -1e9f, acc[mi][j][2])) * li1;
                float w11 = __expf(fmaf((float)mB.y, -1e9f, acc[mi][j][3])) * li1;
                *(float2*)(wr0 + cc) = make_float2(w00, w01);
                *(float2*)(wr1 + cc) = make_float2(w10, w11);
                *(uint2*)(Ks + rl0*LDA + cc)       = make_uint2(f2tf32(w00), f2tf32(w01));
                *(uint2*)(Ks + (rl0 + 8)*LDA + cc) = make_uint2(f2tf32(w10), f2tf32(w11));
            }
        }
        __syncthreads();                 // w tile + V tile ready
        wgemm_v(ctx, Ks, Vs, m0w, n0w, g, t4);
    }

    // ctx writeback (B,H,S,D)
    float* Cb = g_CTX + (bh*SEQ + (size_t)q0)*Dh;
    #pragma unroll
    for (int mi = 0; mi < 2; ++mi)
        #pragma unroll
        for (int half = 0; half < 2; ++half){
            int rl = m0w + mi*16 + half*8 + g;
            #pragma unroll
            for (int j = 0; j < 8; ++j){
                int d = n0w + j*8 + 2*t4;
                *(float2*)(Cb + (size_t)rl*Dh + d) =
                    make_float2(ctx[mi][j][half*2], ctx[mi][j][half*2+1]);
            }
        }
}

// ---------------- output projection (tf32 mma) ----------------
__global__ __launch_bounds__(256) void outproj_tc(const float* __restrict__ Wd,
                                                  const float* __restrict__ bd,
                                                  float* __restrict__ out)
{
    extern __shared__ unsigned sm[];
    unsigned* As = sm;
    unsigned* Bs = sm + 128*LDA;
    const int tid = threadIdx.x, lane = tid & 31, g = lane >> 2, t4 = lane & 3, w = tid >> 5;
    const int m0w = (w & 3) * 32, n0w = (w >> 2) * 64;
    const int m0 = blockIdx.y * 128;
    const int b = m0 >> 11, sbase = m0 & 2047;

    float acc[2][8][4] = {};
    for (int kt = 0; kt < NHEAD; ++kt){
        __syncthreads();
        load_tile(As, g_CTX + (((size_t)(b*NHEAD + kt))*SEQ + sbase)*Dh, Dh, 1.f, tid);
        load_tile(Bs, Wd + (size_t)kt*Dh, NHD, 1.f, tid);   // W rows n=0..127, stride NHD
        __syncthreads();
        wgemm(acc, As, Bs, m0w, n0w, g, t4);
    }
    #pragma unroll
    for (int mi = 0; mi < 2; ++mi)
        #pragma unroll
        for (int half = 0; half < 2; ++half){
            int rl = m0w + mi*16 + half*8 + g;
            float* Or = out + (size_t)(m0 + rl)*Dh;
            #pragma unroll
            for (int j = 0; j < 8; ++j){
                int d = n0w + j*8 + 2*t4;
                float2 v = make_float2(acc[mi][j][half*2]   + bd[d],
                                       acc[mi][j][half*2+1] + bd[d + 1]);
                *(float2*)(Or + d) = v;
            }
        }
}

// ---------------------------------------------------------------------------
extern "C" void kernel_launch(void* const* d_in, const int* in_sizes, int n_in,
                              void* d_out, int out_size)
{
    (void)in_sizes; (void)n_in; (void)out_size;
    const float* x    = (const float*)d_in[0];
    const int*   mask = (const int*)  d_in[1];
    const float* Wq   = (const float*)d_in[2];
    const float* bq   = (const float*)d_in[3];
    const float* Wk   = (const float*)d_in[4];
    const float* bk   = (const float*)d_in[5];
    const float* Wv   = (const float*)d_in[6];
    const float* bv   = (const float*)d_in[7];
    const float* Wd   = (const float*)d_in[8];
    const float* bd   = (const float*)d_in[9];

    float* out     = (float*)d_out;
    float* weights = out + (size_t)NB*SEQ*Dh;

    const size_t smem_proj = (size_t)2*128*LDA*4;                 // 135168
    const size_t smem_attn = (size_t)(2*128*LDA + 128*LDV)*4;     // 204800

    cudaFuncSetAttribute(proj_tc,    cudaFuncAttributeMaxDynamicSharedMemorySize, (int)smem_proj);
    cudaFuncSetAttribute(attn_mma,   cudaFuncAttributeMaxDynamicSharedMemorySize, (int)smem_attn);
    cudaFuncSetAttribute(outproj_tc, cudaFuncAttributeMaxDynamicSharedMemorySize, (int)smem_proj);

    dim3 blk(256);
    dim3 g1(NHD/128, MROWS/128);            // (16, 32)
    proj_tc<<<g1, blk, smem_proj>>>(x, Wq, bq, 0);
    proj_tc<<<g1, blk, smem_proj>>>(x, Wk, bk, 1);
    proj_tc<<<g1, blk, smem_proj>>>(x, Wv, bv, 2);

    dim3 g2(NHEAD, SEQ/128, NB);            // (16, 16, 2) — heads fastest for mask L2 reuse
    attn_mma<<<g2, blk, smem_attn>>>(mask, weights);

    dim3 g3(1, MROWS/128);                  // (1, 32)
    outproj_tc<<<g3, blk, smem_proj>>>(Wd, bd, out);
}

// round 5
// speedup vs baseline: 2.5495x; 1.1240x over previous
#include <cuda_runtime.h>

#define Dh 128
#define NHEAD 16
#define NB 2
#define SEQ 2048
#define NHD (NHEAD*Dh)
#define MROWS (NB*SEQ)

__device__ float g_QKV[3][(size_t)NB*NHEAD*SEQ*Dh];
__device__ float g_CTX[(size_t)NB*NHEAD*SEQ*Dh];
__device__ float g_LINV[(size_t)NB*NHEAD*SEQ];

#define LDA 132     // Q tile ld (and K tile ld): 132 % 32 == 4
#define LDW 68      // w tile ld: 68 % 32 == 4
#define LDV 136     // V tile ld: 136 % 32 == 8

// smem layout (u32 units)
#define OFF_Q   0
#define OFF_KB0 16896            // 128*132
#define OFF_KB1 (16896 + 8704)   // buffers sized 8704 = 128*68 (>= 64*132=8448)
#define OFF_VB0 (16896 + 2*8704)
#define OFF_VB1 (16896 + 3*8704)
#define SMEM_ATTN ((16896 + 4*8704) * 4)   // 206848 B

__device__ __forceinline__ unsigned f2tf32(float f){
    unsigned r; asm("cvt.rna.tf32.f32 %0, %1;" : "=r"(r) : "f"(f)); return r;
}
__device__ __forceinline__ void mma8(float* d, const unsigned* a, unsigned b0, unsigned b1){
    asm volatile("mma.sync.aligned.m16n8k8.row.col.f32.tf32.tf32.f32 "
        "{%0,%1,%2,%3},{%4,%5,%6,%7},{%8,%9},{%0,%1,%2,%3};"
        : "+f"(d[0]), "+f"(d[1]), "+f"(d[2]), "+f"(d[3])
        : "r"(a[0]), "r"(a[1]), "r"(a[2]), "r"(a[3]), "r"(b0), "r"(b1));
}
__device__ __forceinline__ unsigned smem_u32(const void* p){
    unsigned a;
    asm("{ .reg .u64 t; cvta.to.shared.u64 t, %1; cvt.u32.u64 %0, t; }" : "=r"(a) : "l"(p));
    return a;
}
__device__ __forceinline__ void cpa16(unsigned s, const void* g){
    asm volatile("cp.async.ca.shared.global [%0], [%1], 16;" :: "r"(s), "l"(g));
}

// 128x128 f32 -> smem tf32 (RNA), row-major ld=LDA, scaled
__device__ __forceinline__ void load_tile(unsigned* dst, const float* src, int srcStride,
                                          float scale, int tid){
    #pragma unroll
    for (int it = 0; it < 16; ++it){
        int idx = tid + it*256;
        int r = idx >> 5, c = (idx & 31) << 2;
        float4 v = *(const float4*)(src + (size_t)r*srcStride + c);
        uint4 u = make_uint4(f2tf32(v.x*scale), f2tf32(v.y*scale),
                             f2tf32(v.z*scale), f2tf32(v.w*scale));
        *(uint4*)(dst + r*LDA + c) = u;
    }
}

// warp GEMM 128x128x128 (A ld=LDA rows[m][k], B ld=LDA rows[n][k]) for projections
__device__ __forceinline__ void wgemm(float acc[2][8][4], const unsigned* As, const unsigned* Bs,
                                      int m0w, int n0w, int g, int t4){
    #pragma unroll 4
    for (int kk = 0; kk < 16; ++kk){
        unsigned a[2][4];
        #pragma unroll
        for (int mi = 0; mi < 2; ++mi){
            const unsigned* p = As + (m0w + mi*16 + g)*LDA + kk*8 + t4;
            a[mi][0] = p[0];       a[mi][2] = p[4];
            a[mi][1] = p[8*LDA];   a[mi][3] = p[8*LDA + 4];
        }
        #pragma unroll
        for (int j = 0; j < 8; ++j){
            const unsigned* p = Bs + (n0w + j*8 + g)*LDA + kk*8 + t4;
            unsigned b0 = p[0], b1 = p[4];
            mma8(acc[0][j], a[0], b0, b1);
            mma8(acc[1][j], a[1], b0, b1);
        }
    }
}

// ---------------- QKV projection (tf32 mma), Y in (B,H,S,D) ----------------
__global__ __launch_bounds__(256) void proj_tc(const float* __restrict__ X,
                                               const float* __restrict__ W,
                                               const float* __restrict__ bias, int which)
{
    extern __shared__ unsigned sm[];
    unsigned* As = sm;
    unsigned* Bs = sm + 128*LDA;
    const int tid = threadIdx.x, lane = tid & 31, g = lane >> 2, t4 = lane & 3, w = tid >> 5;
    const int m0w = (w & 3) * 32, n0w = (w >> 2) * 64;
    const int m0 = blockIdx.y * 128, n0 = blockIdx.x * 128;

    load_tile(As, X + (size_t)m0*Dh, Dh, 1.f, tid);
    load_tile(Bs, W + (size_t)n0*Dh, Dh, 1.f, tid);
    __syncthreads();

    float acc[2][8][4] = {};
    wgemm(acc, As, Bs, m0w, n0w, g, t4);

    const int b = m0 >> 11, sbase = m0 & 2047, h = n0 >> 7;
    float* Yb = g_QKV[which] + ((size_t)(b*NHEAD + h)*SEQ)*Dh;
    #pragma unroll
    for (int mi = 0; mi < 2; ++mi)
        #pragma unroll
        for (int half = 0; half < 2; ++half){
            int rl = m0w + mi*16 + half*8 + g;
            float* Yr = Yb + (size_t)(sbase + rl)*Dh;
            #pragma unroll
            for (int j = 0; j < 8; ++j){
                int d = n0w + j*8 + 2*t4;
                *(float2*)(Yr + d) = make_float2(acc[mi][j][half*2]   + bias[n0 + d],
                                                 acc[mi][j][half*2+1] + bias[n0 + d + 1]);
            }
        }
}

// ---------------- single-pass fused attention ----------------
__global__ __launch_bounds__(256, 1) void attn_mma(const int* __restrict__ mask,
                                                   float* __restrict__ weights)
{
    extern __shared__ unsigned sm[];
    unsigned* Qs = sm + OFF_Q;
    __shared__ float lpart[128][2];
    __shared__ float linvs[128];

    const int tid = threadIdx.x, lane = tid & 31, g = lane >> 2, t4 = lane & 3, w = tid >> 5;
    const int m0w  = (w & 3) * 32;
    const int n0s  = (w >> 2) * 32;    // QK n-offset (64-wide score tile)
    const int n0d  = (w >> 2) * 64;    // PV n-offset (128-wide d)
    const int h = blockIdx.x, q0 = blockIdx.y * 128, b = blockIdx.z;
    const size_t bh = (size_t)(b*NHEAD + h);
    const float* Qg = g_QKV[0] + bh*SEQ*Dh + (size_t)q0*Dh;
    const float* Kg = g_QKV[1] + bh*SEQ*Dh;
    const float* Vg = g_QKV[2] + bh*SEQ*Dh;
    const int*   mb = mask + (size_t)b*SEQ*SEQ;
    float*       wb = weights + bh*(size_t)SEQ*SEQ;

    const unsigned smbase = smem_u32(sm);
    const unsigned kb_u[2] = { smbase + OFF_KB0*4u, smbase + OFF_KB1*4u };
    const unsigned vb_u[2] = { smbase + OFF_VB0*4u, smbase + OFF_VB1*4u };

    // prologue: stream K0,V0 (raw fp32), load Q (RNA tf32, pre-scaled)
    {
        #pragma unroll
        for (int it2 = 0; it2 < 8; ++it2){
            int idx = tid + it2*256;
            int r = idx >> 5, c = (idx & 31) << 2;
            cpa16(kb_u[0] + (unsigned)(r*LDA + c)*4u, Kg + (size_t)r*Dh + c);
            cpa16(vb_u[0] + (unsigned)(r*LDV + c)*4u, Vg + (size_t)r*Dh + c);
        }
        asm volatile("cp.async.commit_group;");
    }
    load_tile(Qs, Qg, Dh, 0.08838834764831845f, tid);

    float lsum[2][2] = {{0.f,0.f},{0.f,0.f}};
    float ctx[2][8][4] = {};

    for (int it = 0; it < 32; ++it){
        const int t0 = it * 64;
        const int cur = it & 1, nxt = cur ^ 1;
        // issue next K/V tile (into buffers freed by PV_{it-1})
        if (it + 1 < 32){
            const float* Kn = Kg + (size_t)(t0 + 64)*Dh;
            const float* Vn = Vg + (size_t)(t0 + 64)*Dh;
            #pragma unroll
            for (int it2 = 0; it2 < 8; ++it2){
                int idx = tid + it2*256;
                int r = idx >> 5, c = (idx & 31) << 2;
                cpa16(kb_u[nxt] + (unsigned)(r*LDA + c)*4u, Kn + (size_t)r*Dh + c);
                cpa16(vb_u[nxt] + (unsigned)(r*LDV + c)*4u, Vn + (size_t)r*Dh + c);
            }
        }
        asm volatile("cp.async.commit_group;");
        asm volatile("cp.async.wait_group 1;");
        __syncthreads();

        const unsigned* Ks = sm + (cur ? OFF_KB1 : OFF_KB0);
        const unsigned* Vs = sm + (cur ? OFF_VB1 : OFF_VB0);
        unsigned*       Ws = sm + (cur ? OFF_KB1 : OFF_KB0);

        // ---- QK: acc[2][4][4], warp tile 32x32 over 128x64 scores ----
        float acc[2][4][4] = {};
        #pragma unroll 4
        for (int kk = 0; kk < 16; ++kk){
            unsigned a[2][4];
            #pragma unroll
            for (int mi = 0; mi < 2; ++mi){
                const unsigned* p = Qs + (m0w + mi*16 + g)*LDA + kk*8 + t4;
                a[mi][0] = p[0];       a[mi][2] = p[4];
                a[mi][1] = p[8*LDA];   a[mi][3] = p[8*LDA + 4];
            }
            #pragma unroll
            for (int j = 0; j < 4; ++j){
                const unsigned* p = Ks + (n0s + j*8 + g)*LDA + kk*8 + t4;
                unsigned b0 = f2tf32(__uint_as_float(p[0]));    // RNA on raw K
                unsigned b1 = f2tf32(__uint_as_float(p[4]));
                mma8(acc[0][j], a[0], b0, b1);
                mma8(acc[1][j], a[1], b0, b1);
            }
        }
        __syncthreads();    // K reads done -> buffer reusable as w tile

        // ---- epilogue: u = exp(s + mask*-1e9); STG u; STS tf32(u); lsum ----
        #pragma unroll
        for (int mi = 0; mi < 2; ++mi){
            int rl0 = m0w + mi*16 + g;
            int r0  = q0 + rl0;
            const int* mr0 = mb + (size_t)r0*SEQ + t0;
            const int* mr1 = mr0 + 8*SEQ;
            float* wr0 = wb + (size_t)r0*SEQ + t0;
            float* wr1 = wr0 + 8*SEQ;
            #pragma unroll
            for (int j = 0; j < 4; ++j){
                int cc = n0s + j*8 + 2*t4;
                int2 mA = *(const int2*)(mr0 + cc);
                int2 mB = *(const int2*)(mr1 + cc);
                float u00 = __expf(fmaf((float)mA.x, -1e9f, acc[mi][j][0]));
                float u01 = __expf(fmaf((float)mA.y, -1e9f, acc[mi][j][1]));
                float u10 = __expf(fmaf((float)mB.x, -1e9f, acc[mi][j][2]));
                float u11 = __expf(fmaf((float)mB.y, -1e9f, acc[mi][j][3]));
                *(float2*)(wr0 + cc) = make_float2(u00, u01);
                *(float2*)(wr1 + cc) = make_float2(u10, u11);
                lsum[mi][0] += u00 + u01;
                lsum[mi][1] += u10 + u11;
                *(uint2*)(Ws + rl0*LDW + cc)      = make_uint2(f2tf32(u00), f2tf32(u01));
                *(uint2*)(Ws + (rl0 + 8)*LDW + cc)= make_uint2(f2tf32(u10), f2tf32(u11));
            }
        }
        __syncthreads();    // w tile visible (V already resident)

        // ---- PV: ctx += w(128x64, ld=LDW) * V(64x128, ld=LDV) ----
        #pragma unroll 4
        for (int kk = 0; kk < 8; ++kk){
            unsigned a[2][4];
            #pragma unroll
            for (int mi = 0; mi < 2; ++mi){
                const unsigned* p = Ws + (m0w + mi*16 + g)*LDW + kk*8 + t4;
                a[mi][0] = p[0];       a[mi][2] = p[4];
                a[mi][1] = p[8*LDW];   a[mi][3] = p[8*LDW + 4];
            }
            #pragma unroll
            for (int j = 0; j < 8; ++j){
                const unsigned* p = Vs + (kk*8 + t4)*LDV + n0d + j*8 + g;
                unsigned b0 = p[0], b1 = p[4*LDV];   // raw fp32 (trunc tf32) ok for ctx
                mma8(ctx[0][j], a[0], b0, b1);
                mma8(ctx[1][j], a[1], b0, b1);
            }
        }
        __syncthreads();    // PV done -> buffers free for next cp.async
    }

    // ---- reduce l, publish linv ----
    #pragma unroll
    for (int mi = 0; mi < 2; ++mi)
        #pragma unroll
        for (int half = 0; half < 2; ++half){
            float v = lsum[mi][half];
            v += __shfl_xor_sync(0xffffffffu, v, 1);
            v += __shfl_xor_sync(0xffffffffu, v, 2);
            if (t4 == 0) lpart[m0w + mi*16 + half*8 + g][w >> 2] = v;
        }
    __syncthreads();
    if (tid < 128){
        float li = 1.0f / (lpart[tid][0] + lpart[tid][1]);
        linvs[tid] = li;
        g_LINV[bh*SEQ + q0 + tid] = li;
    }
    __syncthreads();

    // ---- ctx * linv -> g_CTX ----
    float* Cb = g_CTX + (bh*SEQ + (size_t)q0)*Dh;
    #pragma unroll
    for (int mi = 0; mi < 2; ++mi)
        #pragma unroll
        for (int half = 0; half < 2; ++half){
            int rl = m0w + mi*16 + half*8 + g;
            float li = linvs[rl];
            #pragma unroll
            for (int j = 0; j < 8; ++j){
                int d = n0d + j*8 + 2*t4;
                *(float2*)(Cb + (size_t)rl*Dh + d) =
                    make_float2(ctx[mi][j][half*2]*li, ctx[mi][j][half*2+1]*li);
            }
        }
}

// ---------------- weights row-normalize: w *= linv[row] ----------------
__global__ __launch_bounds__(256) void norm_w(float* __restrict__ weights)
{
    const float li = g_LINV[blockIdx.x];
    float4* row = (float4*)(weights + (size_t)blockIdx.x * SEQ);
    int t = threadIdx.x;
    float4 a = row[t], c = row[t + 256];
    a.x*=li; a.y*=li; a.z*=li; a.w*=li;
    c.x*=li; c.y*=li; c.z*=li; c.w*=li;
    row[t] = a; row[t + 256] = c;
}

// ---------------- output projection (tf32 mma) ----------------
__global__ __launch_bounds__(256) void outproj_tc(const float* __restrict__ Wd,
                                                  const float* __restrict__ bd,
                                                  float* __restrict__ out)
{
    extern __shared__ unsigned sm[];
    unsigned* As = sm;
    unsigned* Bs = sm + 128*LDA;
    const int tid = threadIdx.x, lane = tid & 31, g = lane >> 2, t4 = lane & 3, w = tid >> 5;
    const int m0w = (w & 3) * 32, n0w = (w >> 2) * 64;
    const int m0 = blockIdx.y * 128;
    const int b = m0 >> 11, sbase = m0 & 2047;

    float acc[2][8][4] = {};
    for (int kt = 0; kt < NHEAD; ++kt){
        __syncthreads();
        load_tile(As, g_CTX + (((size_t)(b*NHEAD + kt))*SEQ + sbase)*Dh, Dh, 1.f, tid);
        load_tile(Bs, Wd + (size_t)kt*Dh, NHD, 1.f, tid);
        __syncthreads();
        wgemm(acc, As, Bs, m0w, n0w, g, t4);
    }
    #pragma unroll
    for (int mi = 0; mi < 2; ++mi)
        #pragma unroll
        for (int half = 0; half < 2; ++half){
            int rl = m0w + mi*16 + half*8 + g;
            float* Or = out + (size_t)(m0 + rl)*Dh;
            #pragma unroll
            for (int j = 0; j < 8; ++j){
                int d = n0w + j*8 + 2*t4;
                *(float2*)(Or + d) = make_float2(acc[mi][j][half*2]   + bd[d],
                                                 acc[mi][j][half*2+1] + bd[d + 1]);
            }
        }
}

// ---------------------------------------------------------------------------
extern "C" void kernel_launch(void* const* d_in, const int* in_sizes, int n_in,
                              void* d_out, int out_size)
{
    (void)in_sizes; (void)n_in; (void)out_size;
    const float* x    = (const float*)d_in[0];
    const int*   mask = (const int*)  d_in[1];
    const float* Wq   = (const float*)d_in[2];
    const float* bq   = (const float*)d_in[3];
    const float* Wk   = (const float*)d_in[4];
    const float* bk   = (const float*)d_in[5];
    const float* Wv   = (const float*)d_in[6];
    const float* bv   = (const float*)d_in[7];
    const float* Wd   = (const float*)d_in[8];
    const float* bd   = (const float*)d_in[9];

    float* out     = (float*)d_out;
    float* weights = out + (size_t)NB*SEQ*Dh;

    const size_t smem_proj = (size_t)2*128*LDA*4;     // 135168
    const size_t smem_attn = SMEM_ATTN;               // 206848

    cudaFuncSetAttribute(proj_tc,    cudaFuncAttributeMaxDynamicSharedMemorySize, (int)smem_proj);
    cudaFuncSetAttribute(attn_mma,   cudaFuncAttributeMaxDynamicSharedMemorySize, (int)smem_attn);
    cudaFuncSetAttribute(outproj_tc, cudaFuncAttributeMaxDynamicSharedMemorySize, (int)smem_proj);

    dim3 blk(256);
    dim3 g1(NHD/128, MROWS/128);            // (16, 32)
    proj_tc<<<g1, blk, smem_proj>>>(x, Wq, bq, 0);
    proj_tc<<<g1, blk, smem_proj>>>(x, Wk, bk, 1);
    proj_tc<<<g1, blk, smem_proj>>>(x, Wv, bv, 2);

    dim3 g2(NHEAD, SEQ/128, NB);            // (16, 16, 2)
    attn_mma<<<g2, blk, smem_attn>>>(mask, weights);

    norm_w<<<NB*NHEAD*SEQ, 256>>>(weights);

    dim3 g3(1, MROWS/128);
    outproj_tc<<<g3, blk, smem_proj>>>(Wd, bd, out);
}